// round 15
// baseline (speedup 1.0000x reference)
#include <cuda_runtime.h>
#include <math.h>
#include <stdint.h>

#define N_NODES 100000
#define N_EDGES 640000
#define N_FEAT  128

#define SCAN_CHUNK 512
#define N_CHUNKS ((N_NODES + SCAN_CHUNK - 1) / SCAN_CHUNK)   // 196

typedef unsigned long long u64;

// ---------------- scratch (device globals; zero-initialized at load) -------
__device__ int   g_cnt[N_NODES];        // invariant: zero at entry of each call
__device__ int   g_offs[N_NODES];
__device__ int   g_cursor[N_NODES];
__device__ int   g_bucket[N_EDGES];     // src per CSR slot
__device__ int   g_partial[N_CHUNKS];
__device__ float g_dinv[N_NODES];
__device__ float g_tmp[(size_t)N_NODES * N_FEAT];

// ---- packed f32x2 helpers (sm_103a FFMA2 path) ----
__device__ __forceinline__ u64 dupf2(float f) {
    u64 r; asm("mov.b64 %0, {%1, %1};" : "=l"(r) : "f"(f)); return r;
}
__device__ __forceinline__ u64 packf2(float lo, float hi) {
    u64 r; asm("mov.b64 %0, {%1, %2};" : "=l"(r) : "f"(lo), "f"(hi)); return r;
}
__device__ __forceinline__ void fmaf2(u64& d, u64 a, u64 b) {
    asm("fma.rn.f32x2 %0, %1, %2, %0;" : "+l"(d) : "l"(a), "l"(b));
}
__device__ __forceinline__ void unpackf2(u64 v, float& lo, float& hi) {
    asm("mov.b64 {%0, %1}, %2;" : "=f"(lo), "=f"(hi) : "l"(v));
}

// ---------------------------------------------------------------------------
// 1) histogram of edge destinations (g_cnt zeroed by invariant)
__global__ void k_hist(const int* __restrict__ ei) {
    int e = blockIdx.x * blockDim.x + threadIdx.x;
    if (e < N_EDGES) atomicAdd(&g_cnt[ei[N_EDGES + e]], 1);
}

// 2a) per-chunk exclusive scan, record chunk totals
__global__ __launch_bounds__(SCAN_CHUNK) void k_scan1() {
    __shared__ int s[SCAN_CHUNK];
    int t = threadIdx.x;
    int gid = blockIdx.x * SCAN_CHUNK + t;
    int v = (gid < N_NODES) ? g_cnt[gid] : 0;
    s[t] = v;
    __syncthreads();
#pragma unroll
    for (int d = 1; d < SCAN_CHUNK; d <<= 1) {
        int add = (t >= d) ? s[t - d] : 0;
        __syncthreads();
        s[t] += add;
        __syncthreads();
    }
    if (gid < N_NODES) g_offs[gid] = s[t] - v;
    if (t == SCAN_CHUNK - 1) g_partial[blockIdx.x] = s[t];
}

// 2b) add chunk base (each block reduces partials itself); cursor; dinv
__global__ __launch_bounds__(SCAN_CHUNK) void k_scan3() {
    __shared__ int sp[16];
    int c = blockIdx.x;
    int t = threadIdx.x;
    int v = (t < c) ? g_partial[t] : 0;   // c < N_CHUNKS <= 512
#pragma unroll
    for (int o = 16; o; o >>= 1) v += __shfl_xor_sync(0xffffffffu, v, o);
    if ((t & 31) == 0) sp[t >> 5] = v;
    __syncthreads();
    if (t < 32) {
        int u = (t < 16) ? sp[t] : 0;
#pragma unroll
        for (int o = 8; o; o >>= 1) u += __shfl_xor_sync(0xffffffffu, u, o);
        if (t == 0) sp[0] = u;
    }
    __syncthreads();
    int base = sp[0];
    int i = c * SCAN_CHUNK + t;
    if (i < N_NODES) {
        int o = g_offs[i] + base;
        g_offs[i] = o;
        g_cursor[i] = o;
        g_dinv[i] = rsqrtf((float)(g_cnt[i] + 1));
    }
}

// 3) bucket fill: CSR-by-destination (src only, 4B stores)
__global__ void k_fill(const int* __restrict__ ei) {
    int e = blockIdx.x * blockDim.x + threadIdx.x;
    if (e >= N_EDGES) return;
    int dst = ei[N_EDGES + e];
    int pos = atomicAdd(&g_cursor[dst], 1);
    g_bucket[pos] = ei[e];
}

// 4) gather: warp per destination node; lane owns one float4 of the 128-row.
//    Also restores g_cnt[node]=0 for the next replay.
__global__ __launch_bounds__(256) void k_gather(const float* __restrict__ x) {
    int t = blockIdx.x * blockDim.x + threadIdx.x;
    int node = t >> 5;
    int lane = t & 31;
    if (node >= N_NODES) return;

    const float4* x4 = reinterpret_cast<const float4*>(x);
    float di = g_dinv[node];
    int beg = g_offs[node];
    int cnt = g_cnt[node];
    if (lane == 0) g_cnt[node] = 0;      // restore invariant

    float4 v = x4[(size_t)node * 32 + lane];
    float dd = di * di;
    float4 acc;
    acc.x = v.x * dd; acc.y = v.y * dd; acc.z = v.z * dd; acc.w = v.w * dd;

    int j = 0;
    for (; j + 4 <= cnt; j += 4) {
        int s0 = g_bucket[beg + j + 0];
        int s1 = g_bucket[beg + j + 1];
        int s2 = g_bucket[beg + j + 2];
        int s3 = g_bucket[beg + j + 3];
        float n0 = di * g_dinv[s0];
        float n1 = di * g_dinv[s1];
        float n2 = di * g_dinv[s2];
        float n3 = di * g_dinv[s3];
        float4 v0 = x4[(size_t)s0 * 32 + lane];
        float4 v1 = x4[(size_t)s1 * 32 + lane];
        float4 v2 = x4[(size_t)s2 * 32 + lane];
        float4 v3 = x4[(size_t)s3 * 32 + lane];
        acc.x = fmaf(v0.x, n0, acc.x); acc.y = fmaf(v0.y, n0, acc.y);
        acc.z = fmaf(v0.z, n0, acc.z); acc.w = fmaf(v0.w, n0, acc.w);
        acc.x = fmaf(v1.x, n1, acc.x); acc.y = fmaf(v1.y, n1, acc.y);
        acc.z = fmaf(v1.z, n1, acc.z); acc.w = fmaf(v1.w, n1, acc.w);
        acc.x = fmaf(v2.x, n2, acc.x); acc.y = fmaf(v2.y, n2, acc.y);
        acc.z = fmaf(v2.z, n2, acc.z); acc.w = fmaf(v2.w, n2, acc.w);
        acc.x = fmaf(v3.x, n3, acc.x); acc.y = fmaf(v3.y, n3, acc.y);
        acc.z = fmaf(v3.z, n3, acc.z); acc.w = fmaf(v3.w, n3, acc.w);
    }
    for (; j < cnt; j++) {
        int s0 = g_bucket[beg + j];
        float n0 = di * g_dinv[s0];
        float4 v0 = x4[(size_t)s0 * 32 + lane];
        acc.x = fmaf(v0.x, n0, acc.x); acc.y = fmaf(v0.y, n0, acc.y);
        acc.z = fmaf(v0.z, n0, acc.z); acc.w = fmaf(v0.w, n0, acc.w);
    }
    reinterpret_cast<float4*>(g_tmp)[(size_t)node * 32 + lane] = acc;
}

// ---------------------------------------------------------------------------
// 5) FFMA2 GEMM + epilogue (R5 structure, packed-f32x2 math):
//    h   = relu(tmp @ W^T + b_conv)   -> h_out [N,128]
//    out = sigmoid(h . w_lin + b_lin) -> out  [N]
#define BM 64
#define BK 16

__global__ __launch_bounds__(256) void k_gemm_fused(
    const float* __restrict__ W,      // [128,128] row-major (out, in)
    const float* __restrict__ bconv,  // [128]
    const float* __restrict__ wlin,   // [128]
    const float* __restrict__ blin,   // [1]
    float* __restrict__ out,          // [N]
    float* __restrict__ h_out)        // [N,128]
{
    __shared__ float As[BK][BM];     // k-major
    __shared__ float Ws[BK][128];    // k-major

    int tid = threadIdx.x;
    int tx = tid & 31;
    int ty = tid >> 5;
    int row0 = blockIdx.x * BM;

    // acc2[mp][n]: packed pair of M rows (2*mp, 2*mp+1) x 4 N cols
    u64 acc2[4][4];
#pragma unroll
    for (int mp = 0; mp < 4; mp++)
#pragma unroll
        for (int n = 0; n < 4; n++) acc2[mp][n] = 0ULL;

    int ar = tid >> 2;          // 0..63
    int ac = (tid & 3) * 4;     // 0,4,8,12

    for (int k0 = 0; k0 < N_FEAT; k0 += BK) {
        int grow = row0 + ar;
        float4 av = make_float4(0.f, 0.f, 0.f, 0.f);
        if (grow < N_NODES)
            av = *reinterpret_cast<const float4*>(&g_tmp[(size_t)grow * N_FEAT + k0 + ac]);
        As[ac + 0][ar] = av.x;
        As[ac + 1][ar] = av.y;
        As[ac + 2][ar] = av.z;
        As[ac + 3][ar] = av.w;
#pragma unroll
        for (int p = 0; p < 2; p++) {
            int jr = ar + p * 64;
            float4 wv = *reinterpret_cast<const float4*>(&W[jr * N_FEAT + k0 + ac]);
            Ws[ac + 0][jr] = wv.x;
            Ws[ac + 1][jr] = wv.y;
            Ws[ac + 2][jr] = wv.z;
            Ws[ac + 3][jr] = wv.w;
        }
        __syncthreads();

#pragma unroll
        for (int k = 0; k < BK; k++) {
            float4 b4 = *reinterpret_cast<const float4*>(&Ws[k][tx * 4]);
            float4 a0 = *reinterpret_cast<const float4*>(&As[k][ty * 8]);
            float4 a1 = *reinterpret_cast<const float4*>(&As[k][ty * 8 + 4]);
            // M-pairs come straight out of the float4 loads (no dup cost)
            u64 am0 = packf2(a0.x, a0.y);
            u64 am1 = packf2(a0.z, a0.w);
            u64 am2 = packf2(a1.x, a1.y);
            u64 am3 = packf2(a1.z, a1.w);
            // B scalars duplicated into both halves
            u64 bd0 = dupf2(b4.x);
            u64 bd1 = dupf2(b4.y);
            u64 bd2 = dupf2(b4.z);
            u64 bd3 = dupf2(b4.w);
            fmaf2(acc2[0][0], am0, bd0); fmaf2(acc2[0][1], am0, bd1);
            fmaf2(acc2[0][2], am0, bd2); fmaf2(acc2[0][3], am0, bd3);
            fmaf2(acc2[1][0], am1, bd0); fmaf2(acc2[1][1], am1, bd1);
            fmaf2(acc2[1][2], am1, bd2); fmaf2(acc2[1][3], am1, bd3);
            fmaf2(acc2[2][0], am2, bd0); fmaf2(acc2[2][1], am2, bd1);
            fmaf2(acc2[2][2], am2, bd2); fmaf2(acc2[2][3], am2, bd3);
            fmaf2(acc2[3][0], am3, bd0); fmaf2(acc2[3][1], am3, bd1);
            fmaf2(acc2[3][2], am3, bd2); fmaf2(acc2[3][3], am3, bd3);
        }
        __syncthreads();
    }

    // unpack accumulators to scalar [8][4]
    float acc[8][4];
#pragma unroll
    for (int mp = 0; mp < 4; mp++)
#pragma unroll
        for (int n = 0; n < 4; n++)
            unpackf2(acc2[mp][n], acc[2 * mp][n], acc[2 * mp + 1][n]);

    float4 bc4 = *reinterpret_cast<const float4*>(&bconv[tx * 4]);
    float4 wl4 = *reinterpret_cast<const float4*>(&wlin[tx * 4]);
    float bcv[4] = {bc4.x, bc4.y, bc4.z, bc4.w};
    float wlv[4] = {wl4.x, wl4.y, wl4.z, wl4.w};
    float blv = blin[0];

#pragma unroll
    for (int m = 0; m < 8; m++) {
        int r = row0 + ty * 8 + m;
        float vals[4];
        float part = 0.0f;
#pragma unroll
        for (int n = 0; n < 4; n++) {
            float v = acc[m][n] + bcv[n];
            v = fmaxf(v, 0.0f);
            vals[n] = v;
            part = fmaf(v, wlv[n], part);
        }
        if (r < N_NODES) {
            float4 hv = make_float4(vals[0], vals[1], vals[2], vals[3]);
            *reinterpret_cast<float4*>(&h_out[(size_t)r * N_FEAT + tx * 4]) = hv;
        }
#pragma unroll
        for (int off = 16; off > 0; off >>= 1)
            part += __shfl_xor_sync(0xffffffffu, part, off);
        if (tx == 0 && r < N_NODES)
            out[r] = 1.0f / (1.0f + expf(-(part + blv)));
    }
}

// ---------------------------------------------------------------------------
extern "C" void kernel_launch(void* const* d_in, const int* in_sizes, int n_in,
                              void* d_out, int out_size) {
    const float* x  = (const float*)d_in[0];
    const int*   ei = (const int*)d_in[1];
    const float* Wc = (const float*)d_in[2];
    const float* bc = (const float*)d_in[3];
    const float* wl = (const float*)d_in[4];
    const float* bl = (const float*)d_in[5];

    float* out  = (float*)d_out;            // [N_NODES]
    float* hbuf = out + N_NODES;            // [N_NODES, 128]

    k_hist<<<(N_EDGES + 255) / 256, 256>>>(ei);
    k_scan1<<<N_CHUNKS, SCAN_CHUNK>>>();
    k_scan3<<<N_CHUNKS, SCAN_CHUNK>>>();
    k_fill<<<(N_EDGES + 255) / 256, 256>>>(ei);
    {
        long long t = (long long)N_NODES * 32;
        k_gather<<<(unsigned)((t + 255) / 256), 256>>>(x);
    }
    k_gemm_fused<<<(N_NODES + BM - 1) / BM, 256>>>(Wc, bc, wl, bl, out, hbuf);
}